// round 6
// baseline (speedup 1.0000x reference)
#include <cuda_runtime.h>
#include <cuda_bf16.h>

#define NV 32000
#define NB 64
#define NL 1024
#define NH 128

// scratch (no allocs allowed)
__device__ float  g_tab[NV * NH];   // [v][128]: ks in 0..63, ke in 64..127
__device__ float2 g_nrm[NV];        // per-vocab (||ks||^2, ||ke||^2)
__device__ float  g_r[NB * NH];     // [b][128]

// ============================================================================
// K1: vocab table. Per CTA: 64 vocab rows, 256 threads, 85KB smem -> 2 CTA/SM.
// ============================================================================
#define K1_XS   0
#define K1_T1   8320
#define K1_WB   12480
#define K1_RED  20800
#define K1_SMEMF 21312

__global__ void __launch_bounds__(256, 2)
k1_kernel(const float* __restrict__ embed,
          const float* __restrict__ W1, const float* __restrict__ b1,
          const float* __restrict__ W2, const float* __restrict__ b2,
          const float* __restrict__ gamma, const float* __restrict__ beta,
          const float* __restrict__ Wsem, const float* __restrict__ Wepi)
{
    extern __shared__ float sm[];
    float* Xs  = sm + K1_XS;    // [h(0..127)][65]
    float* T1p = sm + K1_T1;    // [c(0..63)][65]
    float* Wb  = sm + K1_WB;    // weight staging
    float* red = sm + K1_RED;

    const int tid = threadIdx.x;
    const int v0  = blockIdx.x * 64;
    const int ty  = tid >> 4, tx = tid & 15;

    for (int idx = tid; idx < 64 * 128; idx += 256) {
        int r = idx >> 7, h = idx & 127;
        Xs[h * 65 + r] = __ldg(&embed[(size_t)(v0 + r) * NH + h]);
    }
    __syncthreads();

    float xacc[4][8];
    #pragma unroll
    for (int j = 0; j < 8; j++) {
        float bj = __ldg(&b2[16 * j + tx]);
        #pragma unroll
        for (int i = 0; i < 4; i++)
            xacc[i][j] = Xs[(16 * j + tx) * 65 + 4 * ty + i] + bj;
    }

    for (int p = 0; p < 4; p++) {
        for (int idx = tid; idx < 64 * 128; idx += 256) {
            int k = idx & 127, c = idx >> 7;
            Wb[k * 65 + c] = __ldg(&W1[(p * 64 + c) * NH + k]);
        }
        __syncthreads();

        float t1[4][4];
        #pragma unroll
        for (int i = 0; i < 4; i++)
            #pragma unroll
            for (int j = 0; j < 4; j++) t1[i][j] = 0.f;
        #pragma unroll 8
        for (int k = 0; k < 128; k++) {
            float a[4], b[4];
            #pragma unroll
            for (int i = 0; i < 4; i++) a[i] = Xs[k * 65 + 4 * ty + i];
            #pragma unroll
            for (int j = 0; j < 4; j++) b[j] = Wb[k * 65 + 16 * j + tx];
            #pragma unroll
            for (int i = 0; i < 4; i++)
                #pragma unroll
                for (int j = 0; j < 4; j++) t1[i][j] += a[i] * b[j];
        }
        #pragma unroll
        for (int j = 0; j < 4; j++) {
            int c = 16 * j + tx;
            float bj = __ldg(&b1[p * 64 + c]);
            #pragma unroll
            for (int i = 0; i < 4; i++)
                T1p[c * 65 + 4 * ty + i] = fmaxf(t1[i][j] + bj, 0.f);
        }
        __syncthreads();

        for (int idx = tid; idx < 64 * 128; idx += 256) {
            int kk = idx & 63, c = idx >> 6;
            Wb[kk * 129 + c] = __ldg(&W2[c * 256 + p * 64 + kk]);
        }
        __syncthreads();

        #pragma unroll 8
        for (int kk = 0; kk < 64; kk++) {
            float a[4], b[8];
            #pragma unroll
            for (int i = 0; i < 4; i++) a[i] = T1p[kk * 65 + 4 * ty + i];
            #pragma unroll
            for (int j = 0; j < 8; j++) b[j] = Wb[kk * 129 + 16 * j + tx];
            #pragma unroll
            for (int i = 0; i < 4; i++)
                #pragma unroll
                for (int j = 0; j < 8; j++) xacc[i][j] += a[i] * b[j];
        }
        __syncthreads();
    }

    #pragma unroll
    for (int j = 0; j < 8; j++)
        #pragma unroll
        for (int i = 0; i < 4; i++)
            Xs[(16 * j + tx) * 65 + 4 * ty + i] = xacc[i][j];
    __syncthreads();

    {
        int r = tid & 63, qq = tid >> 6;
        float s1 = 0.f, s2 = 0.f;
        #pragma unroll 8
        for (int hh = 0; hh < 32; hh++) {
            float x = Xs[(qq * 32 + hh) * 65 + r];
            s1 += x; s2 += x * x;
        }
        red[qq * 64 + r]       = s1;
        red[256 + qq * 64 + r] = s2;
        __syncthreads();
        float S1 = red[r] + red[64 + r] + red[128 + r] + red[192 + r];
        float S2 = red[256 + r] + red[320 + r] + red[384 + r] + red[448 + r];
        float mu   = S1 * (1.f / 128.f);
        float var  = S2 * (1.f / 128.f) - mu * mu;
        float rstd = rsqrtf(var + 1e-5f);
        #pragma unroll 8
        for (int hh = 0; hh < 32; hh++) {
            int h = qq * 32 + hh;
            float x = Xs[h * 65 + r];
            Xs[h * 65 + r] = (x - mu) * rstd * __ldg(&gamma[h]) + __ldg(&beta[h]);
        }
    }
    __syncthreads();

    for (int p = 0; p < 2; p++) {
        const float* Wk = p ? Wepi : Wsem;
        for (int idx = tid; idx < 64 * 128; idx += 256) {
            int k = idx & 127, c = idx >> 7;
            Wb[k * 65 + c] = __ldg(&Wk[c * NH + k]);
        }
        __syncthreads();
        float acc[4][4];
        #pragma unroll
        for (int i = 0; i < 4; i++)
            #pragma unroll
            for (int j = 0; j < 4; j++) acc[i][j] = 0.f;
        #pragma unroll 8
        for (int k = 0; k < 128; k++) {
            float a[4], b[4];
            #pragma unroll
            for (int i = 0; i < 4; i++) a[i] = Xs[k * 65 + 4 * ty + i];
            #pragma unroll
            for (int j = 0; j < 4; j++) b[j] = Wb[k * 65 + 16 * j + tx];
            #pragma unroll
            for (int i = 0; i < 4; i++)
                #pragma unroll
                for (int j = 0; j < 4; j++) acc[i][j] += a[i] * b[j];
        }
        #pragma unroll
        for (int i = 0; i < 4; i++)
            #pragma unroll
            for (int j = 0; j < 4; j++)
                g_tab[(size_t)(v0 + 4 * ty + i) * NH + p * 64 + 16 * j + tx] =
                    acc[i][j];
        #pragma unroll
        for (int i = 0; i < 4; i++) {
            float s = acc[i][0] * acc[i][0] + acc[i][1] * acc[i][1]
                    + acc[i][2] * acc[i][2] + acc[i][3] * acc[i][3];
            s += __shfl_xor_sync(0xffffffffu, s, 1);
            s += __shfl_xor_sync(0xffffffffu, s, 2);
            s += __shfl_xor_sync(0xffffffffu, s, 4);
            s += __shfl_xor_sync(0xffffffffu, s, 8);
            if (tx == 0) {
                float* gn = (float*)&g_nrm[v0 + 4 * ty + i];
                gn[p] = s;
            }
        }
        __syncthreads();
    }
}

// ============================================================================
// K2: scan with DEFERRED rank-1 correction.
//   u_{t+1} = inv_{t+1} * ( M_t*k_{t+1}  +  gcoef_t * (k_t . k_{t+1}) * d_t )
// The matvec M_t*k_{t+1} and the M update run OFF the gate's critical path.
// dot(k_t,k_{t+1}) rides the err^2 shfl reduce on the odd-parity lanes.
// 4-slot ring, prefetch depth 2; k col-slices register-rolled (macro 2x unroll).
// ============================================================================
#define K2STEP(T, KC, KN) {                                                    \
    const int par_ = (T) & 1;                                                  \
    if (tid < 128) slotf[((((T) + 2) & 3) << 7) + tid] = pv;                   \
    {   int nt3 = (T) + 3;                                                     \
        float npv = 0.f;                                                       \
        if (tid < 128 && nt3 < NL)                                             \
            npv = __ldg(&g_tab[(size_t)seqs[nt3] * NH + tid]);                 \
        pv = npv; }                                                            \
    {   int ni = ((T) + 2 < NL) ? (T) + 2 : NL - 1;                            \
        fn = __ldg(&g_nrm[seqs[ni]]); }                                        \
    float inv_f = 1.f / fmaxf(sqrtf(part ? fn.y : fn.x), 1e-12f);              \
    {   const float* kb_ = &slotf[((((T) + 1) & 3) << 7) + kbase];             \
        _Pragma("unroll")                                                      \
        for (int c = 0; c < 8; c++) {                                          \
            float4 f4 = *(const float4*)&kb_[4 * c];                           \
            KN[4*c] = f4.x; KN[4*c+1] = f4.y;                                  \
            KN[4*c+2] = f4.z; KN[4*c+3] = f4.w; } }                            \
    float pp;                                                                  \
    {   float p0 = 0.f, p1 = 0.f, p2 = 0.f, p3 = 0.f;                          \
        _Pragma("unroll")                                                      \
        for (int c = 0; c < 8; c++) {                                          \
            p0 += m[4*c]   * KN[4*c];   p1 += m[4*c+1] * KN[4*c+1];            \
            p2 += m[4*c+2] * KN[4*c+2]; p3 += m[4*c+3] * KN[4*c+3]; }          \
        pp = (p0 + p1) + (p2 + p3);                                            \
        pp += __shfl_xor_sync(0xffffffffu, pp, 1); }                           \
    float kel = slotf[(((T) & 3) << 7) + part * 64 + row];                     \
    float dd  = kel - vp;                                                      \
    float rv;                                                                  \
    if (h == 0) rv = dd * dd;                                                  \
    else        rv = kel * slotf[((((T) + 1) & 3) << 7) + part * 64 + row];    \
    rv += __shfl_xor_sync(0xffffffffu, rv, 2);                                 \
    rv += __shfl_xor_sync(0xffffffffu, rv, 4);                                 \
    rv += __shfl_xor_sync(0xffffffffu, rv, 8);                                 \
    rv += __shfl_xor_sync(0xffffffffu, rv, 16);                                \
    if      (lane == 0) wredA[par_][warp] = rv;                                \
    else if (lane == 1) wredB[par_][warp] = rv;                                \
    __syncthreads();                                                           \
    {   float4 a0 = *(const float4*)&wredA[par_][0];                           \
        float4 a1 = *(const float4*)&wredA[par_][4];                           \
        float4 bb = *(const float4*)&wredB[par_][part * 4];                    \
        float es2 = (a0.x + a0.y) + (a0.z + a0.w);                             \
        float ee2 = (a1.x + a1.y) + (a1.z + a1.w);                             \
        float dotp = (bb.x + bb.y) + (bb.z + bb.w);                            \
        bool fire = (es2 >= 0.49f * cn.x) || (ee2 >= 0.49f * cn.y);            \
        float wf = part ? ((float)((T) + 1) * (1.f / (float)NL)) : 1.f;        \
        float a_ = (fire ? 0.05f : 0.f) * wf * inv_c * dd;                     \
        rawv = pp + a_ * dotp;                                                 \
        vp = inv_n * rawv;                                                     \
        _Pragma("unroll")                                                      \
        for (int c = 0; c < 32; c++) m[c] += a_ * KC[c];                       \
    }                                                                          \
    cn = nn; nn = fn; inv_c = inv_n; inv_n = inv_f;                            \
}

__global__ void __launch_bounds__(256, 1)
k2_kernel(const int* __restrict__ seq,
          const float* __restrict__ Wrp, const float* __restrict__ brp)
{
    __shared__ int   seqs[NL];
    __shared__ float slotf[4 * 128];
    __shared__ __align__(16) float wredA[2][8];
    __shared__ __align__(16) float wredB[2][8];
    __shared__ float cbuf[128];

    const int tid  = threadIdx.x;
    const int b    = blockIdx.x;
    const int part = tid >> 7;          // 0 = s, 1 = e
    const int pt   = tid & 127;
    const int row  = pt >> 1;
    const int h    = pt & 1;
    const int lane = tid & 31;
    const int warp = tid >> 5;
    const int kbase = part * 64 + h * 32;

    for (int idx = tid; idx < NL; idx += 256) seqs[idx] = seq[b * NL + idx];
    __syncthreads();

    // preload k_0, k_1 into slots 0,1; pv = k_2; norms n_0, n_1
    float pv;
    if (tid < 128) {
        slotf[tid]       = __ldg(&g_tab[(size_t)seqs[0] * NH + tid]);
        slotf[128 + tid] = __ldg(&g_tab[(size_t)seqs[1] * NH + tid]);
        pv               = __ldg(&g_tab[(size_t)seqs[2] * NH + tid]);
    } else pv = 0.f;
    float2 cn = __ldg(&g_nrm[seqs[0]]);
    float2 nn = __ldg(&g_nrm[seqs[1]]);
    float2 fn;
    float inv_c = 1.f / fmaxf(sqrtf(part ? cn.y : cn.x), 1e-12f);
    float inv_n = 1.f / fmaxf(sqrtf(part ? nn.y : nn.x), 1e-12f);
    __syncthreads();

    float m[32];
    #pragma unroll
    for (int c = 0; c < 32; c++) m[c] = 0.f;
    float vp = 0.f, rawv = 0.f;

    // preload ka = k_0 col slice
    float ka[32], kb[32];
    {
        const float* k0 = &slotf[kbase];
        #pragma unroll
        for (int c = 0; c < 8; c++) {
            float4 f4 = *(const float4*)&k0[4 * c];
            ka[4*c] = f4.x; ka[4*c+1] = f4.y; ka[4*c+2] = f4.z; ka[4*c+3] = f4.w;
        }
    }

    for (int t = 0; t < NL - 2; t += 2) {
        K2STEP(t,     ka, kb);
        K2STEP(t + 1, kb, ka);
    }
    K2STEP(NL - 2, ka, kb);     // t = 1022; rawv = M_final . k_{L-1} per row

    if (h == 0) cbuf[part * 64 + row] = rawv;
    __syncthreads();

    // r = Wrp @ c + brp -> g_r
    {
        int o = tid >> 1, h2 = tid & 1;
        const float* wr = &Wrp[o * NH + h2 * 64];
        const float* cc = &cbuf[h2 * 64];
        float s = 0.f;
        #pragma unroll 8
        for (int mm = 0; mm < 64; mm++) s += __ldg(&wr[mm]) * cc[mm];
        s += __shfl_xor_sync(0xffffffffu, s, 1);
        if (h2 == 0) g_r[b * NH + o] = s + __ldg(&brp[o]);
    }
}

// ============================================================================
// K3: out[64 x 32000] = r @ Wout^T + bout.  250 CTAs, tile 64b x 128v.
// ============================================================================
#define K3_RST 65
#define K3_WST 129
#define K3_WS  (128 * K3_RST)
#define K3_SMEMF (K3_WS + 128 * K3_WST)

__global__ void __launch_bounds__(256, 2)
k3_kernel(const float* __restrict__ Wout, const float* __restrict__ bout,
          float* __restrict__ out)
{
    extern __shared__ float sm[];
    float* rs = sm;
    float* Ws = sm + K3_WS;
    const int tid = threadIdx.x;
    const int v0  = blockIdx.x * 128;
    const int ty  = tid >> 4, tx = tid & 15;

    for (int idx = tid; idx < 64 * 128; idx += 256) {
        int bb = idx >> 7, k = idx & 127;
        rs[k * K3_RST + bb] = g_r[idx];
    }
    for (int idx = tid; idx < 128 * 128; idx += 256) {
        int vv = idx >> 7, k = idx & 127;
        Ws[k * K3_WST + vv] = __ldg(&Wout[(size_t)(v0 + vv) * NH + k]);
    }
    __syncthreads();

    float acc0[4][4], acc1[4][4];
    #pragma unroll
    for (int i = 0; i < 4; i++)
        #pragma unroll
        for (int j = 0; j < 4; j++) { acc0[i][j] = 0.f; acc1[i][j] = 0.f; }

    #pragma unroll 4
    for (int k = 0; k < 128; k++) {
        float a[4], b0[4], b1[4];
        #pragma unroll
        for (int i = 0; i < 4; i++) a[i]  = rs[k * K3_RST + 4 * ty + i];
        #pragma unroll
        for (int j = 0; j < 4; j++) b0[j] = Ws[k * K3_WST + 16 * j + tx];
        #pragma unroll
        for (int j = 0; j < 4; j++) b1[j] = Ws[k * K3_WST + 64 + 16 * j + tx];
        #pragma unroll
        for (int i = 0; i < 4; i++)
            #pragma unroll
            for (int j = 0; j < 4; j++) {
                acc0[i][j] += a[i] * b0[j];
                acc1[i][j] += a[i] * b1[j];
            }
    }

    #pragma unroll
    for (int j = 0; j < 4; j++) {
        float bj0 = __ldg(&bout[v0 + 16 * j + tx]);
        float bj1 = __ldg(&bout[v0 + 64 + 16 * j + tx]);
        #pragma unroll
        for (int i = 0; i < 4; i++) {
            size_t base = (size_t)(4 * ty + i) * NV + v0;
            out[base + 16 * j + tx]      = acc0[i][j] + bj0;
            out[base + 64 + 16 * j + tx] = acc1[i][j] + bj1;
        }
    }
}

// ============================================================================
extern "C" void kernel_launch(void* const* d_in, const int* in_sizes, int n_in,
                              void* d_out, int out_size)
{
    const int*   seq   = (const int*)d_in[0];
    const float* embed = (const float*)d_in[1];
    const float* W1    = (const float*)d_in[2];
    const float* b1    = (const float*)d_in[3];
    const float* W2    = (const float*)d_in[4];
    const float* b2    = (const float*)d_in[5];
    const float* gamma = (const float*)d_in[6];
    const float* beta  = (const float*)d_in[7];
    const float* Wsem  = (const float*)d_in[8];
    const float* Wepi  = (const float*)d_in[9];
    const float* Wrp   = (const float*)d_in[10];
    const float* brp   = (const float*)d_in[11];
    const float* Wout  = (const float*)d_in[12];
    const float* bout  = (const float*)d_in[13];
    float* out = (float*)d_out;

    cudaFuncSetAttribute(k1_kernel, cudaFuncAttributeMaxDynamicSharedMemorySize,
                         K1_SMEMF * (int)sizeof(float));
    cudaFuncSetAttribute(k3_kernel, cudaFuncAttributeMaxDynamicSharedMemorySize,
                         K3_SMEMF * (int)sizeof(float));

    k1_kernel<<<NV / 64, 256, K1_SMEMF * sizeof(float)>>>(
        embed, W1, b1, W2, b2, gamma, beta, Wsem, Wepi);
    k2_kernel<<<NB, 256>>>(seq, Wrp, brp);
    k3_kernel<<<NV / 128, 256, K3_SMEMF * sizeof(float)>>>(Wout, bout, out);
}